// round 3
// baseline (speedup 1.0000x reference)
#include <cuda_runtime.h>
#include <cuda_bf16.h>
#include <cstdint>

// Inputs: 0 positions f32 (N)*3 | 1 cell f32 9 | 2 cutoffs f32 2
//         3 shifts i32 S*3 | 4 ml_idx i32 | 5 mm_idx i32
// Output (f32 flat): [0,2P) idx_i | [2P,4P) idx_j | [4P,10P) offsets(2P x 3)
//                    [10P,12P) d2_full | [12P,16P) masks(2 x 2P)
// P=(S+1)*n_ml*n_mm.  idx_i=[pi,pj], idx_j=[pj,pi], offsets=[-sv,+sv], d2=[d2,d2].
//
// Grid partition: blocks [0,pairBlocks) compute idx/d2/masks (4 pairs/thread,
// all-coalesced float4 stores). Blocks [pairBlocks, ...) pattern-fill the
// offsets region with perfectly coalesced 128B/thread stores (the per-pair
// 48B-strided offsets stores were 44% of all L1 wavefronts).

__device__ __forceinline__ void load_cell(const float* __restrict__ cell,
                                          float c[9]) {
    #pragma unroll
    for (int u = 0; u < 9; u++) c[u] = __ldg(cell + u);
}

__device__ __forceinline__ void shift_vec(const int* __restrict__ shifts, int s,
                                          const float c[9],
                                          float& svx, float& svy, float& svz) {
    float sf0 = 0.f, sf1 = 0.f, sf2 = 0.f;
    if (s > 0) {
        sf0 = (float)__ldg(shifts + (s - 1) * 3 + 0);
        sf1 = (float)__ldg(shifts + (s - 1) * 3 + 1);
        sf2 = (float)__ldg(shifts + (s - 1) * 3 + 2);
    }
    svx = sf0 * c[0] + sf1 * c[3] + sf2 * c[6];
    svy = sf0 * c[1] + sf1 * c[4] + sf2 * c[7];
    svz = sf0 * c[2] + sf1 * c[5] + sf2 * c[8];
}

__global__ __launch_bounds__(256)
void nbrlist_fused(const float* __restrict__ pos,
                   const float* __restrict__ cell,
                   const float* __restrict__ cutoffs,
                   const int*   __restrict__ shifts,
                   const int*   __restrict__ ml_idx,
                   const int*   __restrict__ mm_idx,
                   float* __restrict__ out,
                   int n_ml, int n_mm, int S_img, long long P,
                   long long pairBlocks, int off_aligned)
{
    const long long P0 = (long long)n_ml * n_mm;
    float c[9];
    load_cell(cell, c);

    if (blockIdx.x >= (unsigned)pairBlocks) {
        // ───────── offsets pattern-fill blocks ─────────
        long long t = ((long long)blockIdx.x - pairBlocks) * blockDim.x + threadIdx.x;
        const long long halfF = 3 * P;          // floats per half
        const long long totF  = 6 * P;
        if (off_aligned) {
            // each thread writes 32 consecutive floats (8 float4, 128B)
            long long f = t * 32;
            if (f >= totF) return;
            const bool negh = f < halfF;
            const long long fl = negh ? f : f - halfF;   // local float index
            const int s = (int)(fl / (3 * P0));
            float svx, svy, svz;
            shift_vec(shifts, s, c, svx, svy, svz);
            const float X = negh ? -svx : svx;
            const float Y = negh ? -svy : svy;
            const float Z = negh ? -svz : svz;
            const float4 var[3] = { make_float4(X, Y, Z, X),
                                    make_float4(Y, Z, X, Y),
                                    make_float4(Z, X, Y, Z) };
            int v = (int)((fl >> 2) % 3);
            float4* dst = reinterpret_cast<float4*>(out + 4 * P + (negh ? 0 : halfF) + fl);
            #pragma unroll
            for (int u = 0; u < 8; u++) {
                __stcs(dst + u, var[v]);
                v++; if (v == 3) v = 0;
            }
        } else {
            // generic scalar fallback
            long long f0 = t * 32;
            for (int u = 0; u < 32; u++) {
                long long f = f0 + u;
                if (f >= totF) break;
                const bool negh = f < halfF;
                const long long fl = negh ? f : f - halfF;
                const long long row = fl / 3;
                const int comp = (int)(fl - row * 3);
                const int s = (int)(row / P0);
                float svx, svy, svz;
                shift_vec(shifts, s, c, svx, svy, svz);
                float val = (comp == 0) ? svx : (comp == 1) ? svy : svz;
                if (negh) val = -val;
                out[4 * P + (negh ? 0 : halfF) + fl] = val;
            }
        }
        return;
    }

    // ───────── pairs blocks: idx_i, idx_j, d2, masks ─────────
    long long tid = (long long)blockIdx.x * blockDim.x + threadIdx.x;
    long long p = tid * 4;
    if (p >= P) return;

    int s = (int)(p / P0);
    long long k = p - (long long)s * P0;
    int i  = (int)(k / n_mm);
    int j0 = (int)(k - (long long)i * n_mm);

    const float cut0 = __ldg(cutoffs + 0), cut1 = __ldg(cutoffs + 1);
    const float c0sq = cut0 * cut0, c1sq = cut1 * cut1;

    const long long base_ii = 0;
    const long long base_ij = 2 * P;
    const long long base_d2 = 10 * P;
    const long long base_mk = 12 * P;

    bool fast = (p + 3 < P) && ((k / n_mm) == ((k + 3) / n_mm)) && ((j0 & 3) == 0);

    if (fast) {
        float svx, svy, svz;
        shift_vec(shifts, s, c, svx, svy, svz);

        const int ia = __ldg(ml_idx + i);
        const float pix = __ldg(pos + 3 * ia + 0) + svx;
        const float piy = __ldg(pos + 3 * ia + 1) + svy;
        const float piz = __ldg(pos + 3 * ia + 2) + svz;

        const int4 jv = __ldg(reinterpret_cast<const int4*>(mm_idx + j0));

        float d2v[4], pjf[4];
        pjf[0] = (float)jv.x; pjf[1] = (float)jv.y;
        pjf[2] = (float)jv.z; pjf[3] = (float)jv.w;

        const bool contig = (jv.w == jv.x + 3) && (((3 * jv.x) & 3) == 0);
        if (contig) {
            const float4* pb = reinterpret_cast<const float4*>(pos + 3 * jv.x);
            const float4 v0 = __ldg(pb + 0);
            const float4 v1 = __ldg(pb + 1);
            const float4 v2 = __ldg(pb + 2);
            { const float dx = pix - v0.x, dy = piy - v0.y, dz = piz - v0.z;
              d2v[0] = dx * dx + dy * dy + dz * dz; }
            { const float dx = pix - v0.w, dy = piy - v1.x, dz = piz - v1.y;
              d2v[1] = dx * dx + dy * dy + dz * dz; }
            { const float dx = pix - v1.z, dy = piy - v1.w, dz = piz - v2.x;
              d2v[2] = dx * dx + dy * dy + dz * dz; }
            { const float dx = pix - v2.y, dy = piy - v2.z, dz = piz - v2.w;
              d2v[3] = dx * dx + dy * dy + dz * dz; }
        } else {
            const int jidx[4] = {jv.x, jv.y, jv.z, jv.w};
            #pragma unroll
            for (int u = 0; u < 4; u++) {
                const float dx = pix - __ldg(pos + 3 * jidx[u] + 0);
                const float dy = piy - __ldg(pos + 3 * jidx[u] + 1);
                const float dz = piz - __ldg(pos + 3 * jidx[u] + 2);
                d2v[u] = dx * dx + dy * dy + dz * dz;
            }
        }

        const float fi = (float)ia;
        const float4 v_fi = make_float4(fi, fi, fi, fi);
        const float4 v_pj = make_float4(pjf[0], pjf[1], pjf[2], pjf[3]);
        const float4 v_d2 = make_float4(d2v[0], d2v[1], d2v[2], d2v[3]);

        __stcs(reinterpret_cast<float4*>(out + base_ii + p),     v_fi);
        __stcs(reinterpret_cast<float4*>(out + base_ii + P + p), v_pj);
        __stcs(reinterpret_cast<float4*>(out + base_ij + p),     v_pj);
        __stcs(reinterpret_cast<float4*>(out + base_ij + P + p), v_fi);
        __stcs(reinterpret_cast<float4*>(out + base_d2 + p),     v_d2);
        __stcs(reinterpret_cast<float4*>(out + base_d2 + P + p), v_d2);

        const float4 m0 = make_float4(d2v[0] < c0sq ? 1.f : 0.f,
                                      d2v[1] < c0sq ? 1.f : 0.f,
                                      d2v[2] < c0sq ? 1.f : 0.f,
                                      d2v[3] < c0sq ? 1.f : 0.f);
        const float4 m1 = make_float4(d2v[0] < c1sq ? 1.f : 0.f,
                                      d2v[1] < c1sq ? 1.f : 0.f,
                                      d2v[2] < c1sq ? 1.f : 0.f,
                                      d2v[3] < c1sq ? 1.f : 0.f);
        __stcs(reinterpret_cast<float4*>(out + base_mk + p),         m0);
        __stcs(reinterpret_cast<float4*>(out + base_mk + P + p),     m0);
        __stcs(reinterpret_cast<float4*>(out + base_mk + 2 * P + p), m1);
        __stcs(reinterpret_cast<float4*>(out + base_mk + 3 * P + p), m1);
    } else {
        for (int u = 0; u < 4; u++) {
            long long pp = p + u;
            if (pp >= P) break;
            int ss = (int)(pp / P0);
            long long kk = pp - (long long)ss * P0;
            int ii = (int)(kk / n_mm);
            int jj = (int)(kk - (long long)ii * n_mm);

            float svx, svy, svz;
            shift_vec(shifts, ss, c, svx, svy, svz);

            const int ia = __ldg(ml_idx + ii);
            const int ja = __ldg(mm_idx + jj);
            const float dx = __ldg(pos + 3 * ia + 0) - __ldg(pos + 3 * ja + 0) + svx;
            const float dy = __ldg(pos + 3 * ia + 1) - __ldg(pos + 3 * ja + 1) + svy;
            const float dz = __ldg(pos + 3 * ia + 2) - __ldg(pos + 3 * ja + 2) + svz;
            const float d2 = dx * dx + dy * dy + dz * dz;
            const float fi = (float)ia, fj = (float)ja;

            out[base_ii + pp]     = fi;
            out[base_ii + P + pp] = fj;
            out[base_ij + pp]     = fj;
            out[base_ij + P + pp] = fi;
            out[base_d2 + pp]     = d2;
            out[base_d2 + P + pp] = d2;
            const float m0 = d2 < c0sq ? 1.f : 0.f;
            const float m1 = d2 < c1sq ? 1.f : 0.f;
            out[base_mk + pp]         = m0;
            out[base_mk + P + pp]     = m0;
            out[base_mk + 2 * P + pp] = m1;
            out[base_mk + 3 * P + pp] = m1;
        }
    }
}

extern "C" void kernel_launch(void* const* d_in, const int* in_sizes, int n_in,
                              void* d_out, int out_size)
{
    const float* pos     = (const float*)d_in[0];
    const float* cell    = (const float*)d_in[1];
    const float* cutoffs = (const float*)d_in[2];
    const int*   shifts  = (const int*)d_in[3];
    const int*   ml_idx  = (const int*)d_in[4];
    const int*   mm_idx  = (const int*)d_in[5];

    const int n_ml  = in_sizes[4];
    const int n_mm  = in_sizes[5];
    const int S     = in_sizes[3] / 3;
    const int S_img = S + 1;
    const long long P0 = (long long)n_ml * n_mm;
    const long long P  = (long long)S_img * P0;

    const int threads = 256;
    const long long n_groups   = (P + 3) / 4;
    const long long pairBlocks = (n_groups + threads - 1) / threads;

    // offsets: 6P floats, 32 floats per thread
    const int off_aligned = ((P0 % 32) == 0) && ((P % 32) == 0) ? 1 : 0;
    const long long offFloats  = 6 * P;
    const long long offThreads = (offFloats + 31) / 32;
    const long long offBlocks  = (offThreads + threads - 1) / threads;

    const long long totalBlocks = pairBlocks + offBlocks;

    nbrlist_fused<<<(unsigned)totalBlocks, threads>>>(
        pos, cell, cutoffs, shifts, ml_idx, mm_idx,
        (float*)d_out, n_ml, n_mm, S_img, P, pairBlocks, off_aligned);
}

// round 4
// speedup vs baseline: 1.5555x; 1.5555x over previous
#include <cuda_runtime.h>
#include <cuda_bf16.h>
#include <cstdint>

// Inputs: 0 positions f32 (N)*3 | 1 cell f32 9 | 2 cutoffs f32 2
//         3 shifts i32 S*3 | 4 ml_idx i32 | 5 mm_idx i32
// Output (f32 flat): [0,2P) idx_i | [2P,4P) idx_j | [4P,10P) offsets(2P x 3)
//                    [10P,12P) d2_full | [12P,16P) masks(2 x 2P)
// P=(S+1)*n_ml*n_mm.  idx_i=[pi,pj], idx_j=[pj,pi], offsets=[-sv,+sv], d2=[d2,d2].
//
// Blocks [0,pairBlocks): idx/d2/masks, 4 pairs/thread, coalesced float4 stores.
// Blocks [pairBlocks,..): offsets pattern-fill. Block owns 2048 consecutive
// float4s; lane t writes f4 = base + t + u*256 (u<8) -> every STG.128 is a
// contiguous 512B warp transaction (R3 had 128B lane stride = 8x wavefronts).

__device__ __forceinline__ void load_cell(const float* __restrict__ cell,
                                          float c[9]) {
    #pragma unroll
    for (int u = 0; u < 9; u++) c[u] = __ldg(cell + u);
}

__device__ __forceinline__ void shift_vec(const int* __restrict__ shifts, int s,
                                          const float c[9],
                                          float& svx, float& svy, float& svz) {
    float sf0 = 0.f, sf1 = 0.f, sf2 = 0.f;
    if (s > 0) {
        sf0 = (float)__ldg(shifts + (s - 1) * 3 + 0);
        sf1 = (float)__ldg(shifts + (s - 1) * 3 + 1);
        sf2 = (float)__ldg(shifts + (s - 1) * 3 + 2);
    }
    svx = sf0 * c[0] + sf1 * c[3] + sf2 * c[6];
    svy = sf0 * c[1] + sf1 * c[4] + sf2 * c[7];
    svz = sf0 * c[2] + sf1 * c[5] + sf2 * c[8];
}

__global__ __launch_bounds__(256)
void nbrlist_fused(const float* __restrict__ pos,
                   const float* __restrict__ cell,
                   const float* __restrict__ cutoffs,
                   const int*   __restrict__ shifts,
                   const int*   __restrict__ ml_idx,
                   const int*   __restrict__ mm_idx,
                   float* __restrict__ out,
                   int n_ml, int n_mm, int S_img, long long P,
                   long long pairBlocks, int off_aligned)
{
    const long long P0 = (long long)n_ml * n_mm;
    float c[9];
    load_cell(cell, c);

    if (blockIdx.x >= (unsigned)pairBlocks) {
        // ───────── offsets pattern-fill ─────────
        const long long fb = (long long)blockIdx.x - pairBlocks;
        const long long tot4 = (6 * P) >> 2;          // total float4s in region
        const long long base4 = fb * 2048;            // this block's first float4
        if (base4 >= tot4) return;
        float4* dst = reinterpret_cast<float4*>(out + 4 * P);

        if (off_aligned) {
            // whole block lies in one (half, image) segment
            const long long fbase = base4 * 4;        // float offset in region
            const long long halfF = 3 * P;
            const bool negh = fbase < halfF;
            const long long fl = negh ? fbase : fbase - halfF;
            const int s = (int)(fl / (3 * P0));
            float svx, svy, svz;
            shift_vec(shifts, s, c, svx, svy, svz);
            const float X = negh ? -svx : svx;
            const float Y = negh ? -svy : svy;
            const float Z = negh ? -svz : svz;
            const float4 var[3] = { make_float4(X, Y, Z, X),
                                    make_float4(Y, Z, X, Y),
                                    make_float4(Z, X, Y, Z) };
            long long f4 = base4 + threadIdx.x;
            int v = (int)(f4 % 3);                    // 4*f4 ≡ f4 (mod 3)
            #pragma unroll
            for (int u = 0; u < 8; u++) {
                if (f4 < tot4) __stcs(dst + f4, var[v]);
                f4 += 256;                            // +256 ≡ +1 (mod 3)
                v++; if (v == 3) v = 0;
            }
        } else {
            // scalar fallback
            const long long halfF = 3 * P;
            for (int u = 0; u < 8; u++) {
                long long f4 = base4 + threadIdx.x + (long long)u * 256;
                if (f4 >= tot4) break;
                #pragma unroll
                for (int w = 0; w < 4; w++) {
                    long long f = f4 * 4 + w;
                    const bool negh = f < halfF;
                    const long long fl = negh ? f : f - halfF;
                    const long long row = fl / 3;
                    const int comp = (int)(fl - row * 3);
                    const int s = (int)(row / P0);
                    float svx, svy, svz;
                    shift_vec(shifts, s, c, svx, svy, svz);
                    float val = (comp == 0) ? svx : (comp == 1) ? svy : svz;
                    if (negh) val = -val;
                    out[4 * P + f] = val;
                }
            }
        }
        return;
    }

    // ───────── pairs: idx_i, idx_j, d2, masks ─────────
    long long tid = (long long)blockIdx.x * blockDim.x + threadIdx.x;
    long long p = tid * 4;
    if (p >= P) return;

    int s = (int)(p / P0);
    long long k = p - (long long)s * P0;
    int i  = (int)(k / n_mm);
    int j0 = (int)(k - (long long)i * n_mm);

    const float cut0 = __ldg(cutoffs + 0), cut1 = __ldg(cutoffs + 1);
    const float c0sq = cut0 * cut0, c1sq = cut1 * cut1;

    const long long base_ii = 0;
    const long long base_ij = 2 * P;
    const long long base_d2 = 10 * P;
    const long long base_mk = 12 * P;

    bool fast = (p + 3 < P) && ((k / n_mm) == ((k + 3) / n_mm)) && ((j0 & 3) == 0);

    if (fast) {
        float svx, svy, svz;
        shift_vec(shifts, s, c, svx, svy, svz);

        const int ia = __ldg(ml_idx + i);
        const float pix = __ldg(pos + 3 * ia + 0) + svx;
        const float piy = __ldg(pos + 3 * ia + 1) + svy;
        const float piz = __ldg(pos + 3 * ia + 2) + svz;

        const int4 jv = __ldg(reinterpret_cast<const int4*>(mm_idx + j0));

        float d2v[4], pjf[4];
        pjf[0] = (float)jv.x; pjf[1] = (float)jv.y;
        pjf[2] = (float)jv.z; pjf[3] = (float)jv.w;

        const bool contig = (jv.w == jv.x + 3) && (((3 * jv.x) & 3) == 0);
        if (contig) {
            const float4* pb = reinterpret_cast<const float4*>(pos + 3 * jv.x);
            const float4 v0 = __ldg(pb + 0);
            const float4 v1 = __ldg(pb + 1);
            const float4 v2 = __ldg(pb + 2);
            { const float dx = pix - v0.x, dy = piy - v0.y, dz = piz - v0.z;
              d2v[0] = dx * dx + dy * dy + dz * dz; }
            { const float dx = pix - v0.w, dy = piy - v1.x, dz = piz - v1.y;
              d2v[1] = dx * dx + dy * dy + dz * dz; }
            { const float dx = pix - v1.z, dy = piy - v1.w, dz = piz - v2.x;
              d2v[2] = dx * dx + dy * dy + dz * dz; }
            { const float dx = pix - v2.y, dy = piy - v2.z, dz = piz - v2.w;
              d2v[3] = dx * dx + dy * dy + dz * dz; }
        } else {
            const int jidx[4] = {jv.x, jv.y, jv.z, jv.w};
            #pragma unroll
            for (int u = 0; u < 4; u++) {
                const float dx = pix - __ldg(pos + 3 * jidx[u] + 0);
                const float dy = piy - __ldg(pos + 3 * jidx[u] + 1);
                const float dz = piz - __ldg(pos + 3 * jidx[u] + 2);
                d2v[u] = dx * dx + dy * dy + dz * dz;
            }
        }

        const float fi = (float)ia;
        const float4 v_fi = make_float4(fi, fi, fi, fi);
        const float4 v_pj = make_float4(pjf[0], pjf[1], pjf[2], pjf[3]);
        const float4 v_d2 = make_float4(d2v[0], d2v[1], d2v[2], d2v[3]);

        __stcs(reinterpret_cast<float4*>(out + base_ii + p),     v_fi);
        __stcs(reinterpret_cast<float4*>(out + base_ii + P + p), v_pj);
        __stcs(reinterpret_cast<float4*>(out + base_ij + p),     v_pj);
        __stcs(reinterpret_cast<float4*>(out + base_ij + P + p), v_fi);
        __stcs(reinterpret_cast<float4*>(out + base_d2 + p),     v_d2);
        __stcs(reinterpret_cast<float4*>(out + base_d2 + P + p), v_d2);

        const float4 m0 = make_float4(d2v[0] < c0sq ? 1.f : 0.f,
                                      d2v[1] < c0sq ? 1.f : 0.f,
                                      d2v[2] < c0sq ? 1.f : 0.f,
                                      d2v[3] < c0sq ? 1.f : 0.f);
        const float4 m1 = make_float4(d2v[0] < c1sq ? 1.f : 0.f,
                                      d2v[1] < c1sq ? 1.f : 0.f,
                                      d2v[2] < c1sq ? 1.f : 0.f,
                                      d2v[3] < c1sq ? 1.f : 0.f);
        __stcs(reinterpret_cast<float4*>(out + base_mk + p),         m0);
        __stcs(reinterpret_cast<float4*>(out + base_mk + P + p),     m0);
        __stcs(reinterpret_cast<float4*>(out + base_mk + 2 * P + p), m1);
        __stcs(reinterpret_cast<float4*>(out + base_mk + 3 * P + p), m1);
    } else {
        for (int u = 0; u < 4; u++) {
            long long pp = p + u;
            if (pp >= P) break;
            int ss = (int)(pp / P0);
            long long kk = pp - (long long)ss * P0;
            int ii = (int)(kk / n_mm);
            int jj = (int)(kk - (long long)ii * n_mm);

            float svx, svy, svz;
            shift_vec(shifts, ss, c, svx, svy, svz);

            const int ia = __ldg(ml_idx + ii);
            const int ja = __ldg(mm_idx + jj);
            const float dx = __ldg(pos + 3 * ia + 0) - __ldg(pos + 3 * ja + 0) + svx;
            const float dy = __ldg(pos + 3 * ia + 1) - __ldg(pos + 3 * ja + 1) + svy;
            const float dz = __ldg(pos + 3 * ia + 2) - __ldg(pos + 3 * ja + 2) + svz;
            const float d2 = dx * dx + dy * dy + dz * dz;
            const float fi = (float)ia, fj = (float)ja;

            out[base_ii + pp]     = fi;
            out[base_ii + P + pp] = fj;
            out[base_ij + pp]     = fj;
            out[base_ij + P + pp] = fi;
            out[base_d2 + pp]     = d2;
            out[base_d2 + P + pp] = d2;
            const float m0 = d2 < c0sq ? 1.f : 0.f;
            const float m1 = d2 < c1sq ? 1.f : 0.f;
            out[base_mk + pp]         = m0;
            out[base_mk + P + pp]     = m0;
            out[base_mk + 2 * P + pp] = m1;
            out[base_mk + 3 * P + pp] = m1;
        }
    }
}

extern "C" void kernel_launch(void* const* d_in, const int* in_sizes, int n_in,
                              void* d_out, int out_size)
{
    const float* pos     = (const float*)d_in[0];
    const float* cell    = (const float*)d_in[1];
    const float* cutoffs = (const float*)d_in[2];
    const int*   shifts  = (const int*)d_in[3];
    const int*   ml_idx  = (const int*)d_in[4];
    const int*   mm_idx  = (const int*)d_in[5];

    const int n_ml  = in_sizes[4];
    const int n_mm  = in_sizes[5];
    const int S     = in_sizes[3] / 3;
    const int S_img = S + 1;
    const long long P0 = (long long)n_ml * n_mm;
    const long long P  = (long long)S_img * P0;

    const int threads = 256;
    const long long n_groups   = (P + 3) / 4;
    const long long pairBlocks = (n_groups + threads - 1) / threads;

    // fill blocks: 2048 float4s (8192 floats) per block.
    // Aligned iff every block lies in one (half, image) segment:
    // 8192 | 3*P0 and 8192 | 3*P, and region start 4P is float4-aligned.
    const int off_aligned = (((3 * P0) % 8192) == 0) && (((3 * P) % 8192) == 0)
                            && ((P % 4) == 0) ? 1 : 0;
    const long long tot4      = (6 * P) / 4;
    const long long offBlocks = (tot4 + 2047) / 2048;

    const long long totalBlocks = pairBlocks + offBlocks;

    nbrlist_fused<<<(unsigned)totalBlocks, threads>>>(
        pos, cell, cutoffs, shifts, ml_idx, mm_idx,
        (float*)d_out, n_ml, n_mm, S_img, P, pairBlocks, off_aligned);
}

// round 5
// speedup vs baseline: 1.5577x; 1.0014x over previous
#include <cuda_runtime.h>
#include <cuda_bf16.h>
#include <cstdint>

// Inputs: 0 positions f32 (N)*3 | 1 cell f32 9 | 2 cutoffs f32 2
//         3 shifts i32 S*3 | 4 ml_idx i32 | 5 mm_idx i32
// Output (f32 flat): [0,2P) idx_i | [2P,4P) idx_j | [4P,10P) offsets(2P x 3)
//                    [10P,12P) d2_full | [12P,16P) masks(2 x 2P)
// P=(S+1)*n_ml*n_mm.  idx_i=[pi,pj], idx_j=[pj,pi], offsets=[-sv,+sv], d2=[d2,d2].
//
// Pair blocks (fast mode): block = (i, 1024-j chunk). Each thread loads its 4
// j-positions ONCE, then loops over all S_img images -> position-load L1
// wavefronts amortized 14x; pair path becomes stores-only. Fill blocks
// pattern-fill the offsets region with fully coalesced 512B warp stores.

__device__ __forceinline__ void load_cell(const float* __restrict__ cell,
                                          float c[9]) {
    #pragma unroll
    for (int u = 0; u < 9; u++) c[u] = __ldg(cell + u);
}

__device__ __forceinline__ void shift_vec(const int* __restrict__ shifts, int s,
                                          const float c[9],
                                          float& svx, float& svy, float& svz) {
    float sf0 = 0.f, sf1 = 0.f, sf2 = 0.f;
    if (s > 0) {
        sf0 = (float)__ldg(shifts + (s - 1) * 3 + 0);
        sf1 = (float)__ldg(shifts + (s - 1) * 3 + 1);
        sf2 = (float)__ldg(shifts + (s - 1) * 3 + 2);
    }
    svx = sf0 * c[0] + sf1 * c[3] + sf2 * c[6];
    svy = sf0 * c[1] + sf1 * c[4] + sf2 * c[7];
    svz = sf0 * c[2] + sf1 * c[5] + sf2 * c[8];
}

__device__ __forceinline__ void offsets_fill(const int* __restrict__ shifts,
                                             const float c[9],
                                             float* __restrict__ out,
                                             long long fb, long long P,
                                             long long P0, int off_aligned)
{
    const long long tot4 = (6 * P) >> 2;
    const long long base4 = fb * 2048;
    if (base4 >= tot4) return;
    float4* dst = reinterpret_cast<float4*>(out + 4 * P);
    const long long halfF = 3 * P;

    if (off_aligned) {
        const long long fbase = base4 * 4;
        const bool negh = fbase < halfF;
        const long long fl = negh ? fbase : fbase - halfF;
        const int s = (int)(fl / (3 * P0));
        float svx, svy, svz;
        shift_vec(shifts, s, c, svx, svy, svz);
        const float X = negh ? -svx : svx;
        const float Y = negh ? -svy : svy;
        const float Z = negh ? -svz : svz;
        const float4 var[3] = { make_float4(X, Y, Z, X),
                                make_float4(Y, Z, X, Y),
                                make_float4(Z, X, Y, Z) };
        long long f4 = base4 + threadIdx.x;
        int v = (int)(f4 % 3);
        #pragma unroll
        for (int u = 0; u < 8; u++) {
            if (f4 < tot4) __stcs(dst + f4, var[v]);
            f4 += 256;
            v++; if (v == 3) v = 0;
        }
    } else {
        for (int u = 0; u < 8; u++) {
            long long f4 = base4 + threadIdx.x + (long long)u * 256;
            if (f4 >= tot4) break;
            #pragma unroll
            for (int w = 0; w < 4; w++) {
                long long f = f4 * 4 + w;
                const bool negh = f < halfF;
                const long long fl = negh ? f : f - halfF;
                const long long row = fl / 3;
                const int comp = (int)(fl - row * 3);
                const int s = (int)(row / P0);
                float svx, svy, svz;
                shift_vec(shifts, s, c, svx, svy, svz);
                float val = (comp == 0) ? svx : (comp == 1) ? svy : svz;
                if (negh) val = -val;
                out[4 * P + f] = val;
            }
        }
    }
}

// ───────────────────────── fast kernel: s-loop amortization ─────────────────
__global__ __launch_bounds__(256)
void nbrlist_sloop(const float* __restrict__ pos,
                   const float* __restrict__ cell,
                   const float* __restrict__ cutoffs,
                   const int*   __restrict__ shifts,
                   const int*   __restrict__ ml_idx,
                   const int*   __restrict__ mm_idx,
                   float* __restrict__ out,
                   int n_ml, int n_mm, int S_img, long long P,
                   long long pairBlocks, int jchunks, int off_aligned)
{
    const long long P0 = (long long)n_ml * n_mm;
    float c[9];
    load_cell(cell, c);

    if (blockIdx.x >= (unsigned)pairBlocks) {
        offsets_fill(shifts, c, out, (long long)blockIdx.x - pairBlocks,
                     P, P0, off_aligned);
        return;
    }

    // pair block: fixed i, 1024 consecutive j, loop over all images
    const int bi = (int)blockIdx.x;
    const int i  = bi / jchunks;
    const int jc = bi - i * jchunks;
    const int j0 = jc * 1024 + (int)threadIdx.x * 4;

    const float cut0 = __ldg(cutoffs + 0), cut1 = __ldg(cutoffs + 1);
    const float c0sq = cut0 * cut0, c1sq = cut1 * cut1;

    const int ia = __ldg(ml_idx + i);
    const float pix0 = __ldg(pos + 3 * ia + 0);
    const float piy0 = __ldg(pos + 3 * ia + 1);
    const float piz0 = __ldg(pos + 3 * ia + 2);

    const int4 jv = __ldg(reinterpret_cast<const int4*>(mm_idx + j0));
    float pjx[4], pjy[4], pjz[4], pjf[4];
    pjf[0] = (float)jv.x; pjf[1] = (float)jv.y;
    pjf[2] = (float)jv.z; pjf[3] = (float)jv.w;

    const bool contig = (jv.w == jv.x + 3) && (((3 * jv.x) & 3) == 0);
    if (contig) {
        const float4* pb = reinterpret_cast<const float4*>(pos + 3 * jv.x);
        const float4 v0 = __ldg(pb + 0);
        const float4 v1 = __ldg(pb + 1);
        const float4 v2 = __ldg(pb + 2);
        pjx[0] = v0.x; pjy[0] = v0.y; pjz[0] = v0.z;
        pjx[1] = v0.w; pjy[1] = v1.x; pjz[1] = v1.y;
        pjx[2] = v1.z; pjy[2] = v1.w; pjz[2] = v2.x;
        pjx[3] = v2.y; pjy[3] = v2.z; pjz[3] = v2.w;
    } else {
        const int jidx[4] = {jv.x, jv.y, jv.z, jv.w};
        #pragma unroll
        for (int u = 0; u < 4; u++) {
            pjx[u] = __ldg(pos + 3 * jidx[u] + 0);
            pjy[u] = __ldg(pos + 3 * jidx[u] + 1);
            pjz[u] = __ldg(pos + 3 * jidx[u] + 2);
        }
    }

    const float fi = (float)ia;
    const float4 v_fi = make_float4(fi, fi, fi, fi);
    const float4 v_pj = make_float4(pjf[0], pjf[1], pjf[2], pjf[3]);

    const long long base_ij = 2 * P;
    const long long base_d2 = 10 * P;
    const long long base_mk = 12 * P;
    const long long prow = (long long)i * n_mm + j0;

    for (int s = 0; s < S_img; s++) {
        float svx, svy, svz;
        shift_vec(shifts, s, c, svx, svy, svz);
        const float pix = pix0 + svx;
        const float piy = piy0 + svy;
        const float piz = piz0 + svz;

        float d2v[4];
        #pragma unroll
        for (int u = 0; u < 4; u++) {
            const float dx = pix - pjx[u];
            const float dy = piy - pjy[u];
            const float dz = piz - pjz[u];
            d2v[u] = dx * dx + dy * dy + dz * dz;
        }

        const long long p = (long long)s * P0 + prow;
        const float4 v_d2 = make_float4(d2v[0], d2v[1], d2v[2], d2v[3]);

        __stcs(reinterpret_cast<float4*>(out + p),               v_fi);
        __stcs(reinterpret_cast<float4*>(out + P + p),           v_pj);
        __stcs(reinterpret_cast<float4*>(out + base_ij + p),     v_pj);
        __stcs(reinterpret_cast<float4*>(out + base_ij + P + p), v_fi);
        __stcs(reinterpret_cast<float4*>(out + base_d2 + p),     v_d2);
        __stcs(reinterpret_cast<float4*>(out + base_d2 + P + p), v_d2);

        const float4 m0 = make_float4(d2v[0] < c0sq ? 1.f : 0.f,
                                      d2v[1] < c0sq ? 1.f : 0.f,
                                      d2v[2] < c0sq ? 1.f : 0.f,
                                      d2v[3] < c0sq ? 1.f : 0.f);
        const float4 m1 = make_float4(d2v[0] < c1sq ? 1.f : 0.f,
                                      d2v[1] < c1sq ? 1.f : 0.f,
                                      d2v[2] < c1sq ? 1.f : 0.f,
                                      d2v[3] < c1sq ? 1.f : 0.f);
        __stcs(reinterpret_cast<float4*>(out + base_mk + p),         m0);
        __stcs(reinterpret_cast<float4*>(out + base_mk + P + p),     m0);
        __stcs(reinterpret_cast<float4*>(out + base_mk + 2 * P + p), m1);
        __stcs(reinterpret_cast<float4*>(out + base_mk + 3 * P + p), m1);
    }
}

// ───────────────────────── generic fallback kernel (R4 style) ──────────────
__global__ __launch_bounds__(256)
void nbrlist_generic(const float* __restrict__ pos,
                     const float* __restrict__ cell,
                     const float* __restrict__ cutoffs,
                     const int*   __restrict__ shifts,
                     const int*   __restrict__ ml_idx,
                     const int*   __restrict__ mm_idx,
                     float* __restrict__ out,
                     int n_ml, int n_mm, int S_img, long long P,
                     long long pairBlocks, int off_aligned)
{
    const long long P0 = (long long)n_ml * n_mm;
    float c[9];
    load_cell(cell, c);

    if (blockIdx.x >= (unsigned)pairBlocks) {
        offsets_fill(shifts, c, out, (long long)blockIdx.x - pairBlocks,
                     P, P0, off_aligned);
        return;
    }

    long long tid = (long long)blockIdx.x * blockDim.x + threadIdx.x;
    long long p0 = tid * 4;
    if (p0 >= P) return;

    const float cut0 = __ldg(cutoffs + 0), cut1 = __ldg(cutoffs + 1);
    const float c0sq = cut0 * cut0, c1sq = cut1 * cut1;

    for (int u = 0; u < 4; u++) {
        long long pp = p0 + u;
        if (pp >= P) break;
        int ss = (int)(pp / P0);
        long long kk = pp - (long long)ss * P0;
        int ii = (int)(kk / n_mm);
        int jj = (int)(kk - (long long)ii * n_mm);

        float svx, svy, svz;
        shift_vec(shifts, ss, c, svx, svy, svz);

        const int ia = __ldg(ml_idx + ii);
        const int ja = __ldg(mm_idx + jj);
        const float dx = __ldg(pos + 3 * ia + 0) - __ldg(pos + 3 * ja + 0) + svx;
        const float dy = __ldg(pos + 3 * ia + 1) - __ldg(pos + 3 * ja + 1) + svy;
        const float dz = __ldg(pos + 3 * ia + 2) - __ldg(pos + 3 * ja + 2) + svz;
        const float d2 = dx * dx + dy * dy + dz * dz;
        const float fi = (float)ia, fj = (float)ja;

        out[pp]         = fi;
        out[P + pp]     = fj;
        out[2 * P + pp] = fj;
        out[3 * P + pp] = fi;
        out[10 * P + pp]     = d2;
        out[10 * P + P + pp] = d2;
        const float m0 = d2 < c0sq ? 1.f : 0.f;
        const float m1 = d2 < c1sq ? 1.f : 0.f;
        out[12 * P + pp]         = m0;
        out[12 * P + P + pp]     = m0;
        out[12 * P + 2 * P + pp] = m1;
        out[12 * P + 3 * P + pp] = m1;
    }
}

extern "C" void kernel_launch(void* const* d_in, const int* in_sizes, int n_in,
                              void* d_out, int out_size)
{
    const float* pos     = (const float*)d_in[0];
    const float* cell    = (const float*)d_in[1];
    const float* cutoffs = (const float*)d_in[2];
    const int*   shifts  = (const int*)d_in[3];
    const int*   ml_idx  = (const int*)d_in[4];
    const int*   mm_idx  = (const int*)d_in[5];

    const int n_ml  = in_sizes[4];
    const int n_mm  = in_sizes[5];
    const int S     = in_sizes[3] / 3;
    const int S_img = S + 1;
    const long long P0 = (long long)n_ml * n_mm;
    const long long P  = (long long)S_img * P0;

    const int threads = 256;

    const long long tot4      = (6 * P) / 4;
    const long long offBlocks = (tot4 + 2047) / 2048;
    const int off_aligned = (((3 * P0) % 8192) == 0) && (((3 * P) % 8192) == 0)
                            && ((P % 4) == 0) ? 1 : 0;

    const bool fast_ok = (n_mm % 1024 == 0) && ((P % 4) == 0);

    if (fast_ok) {
        const int jchunks = n_mm / 1024;
        const long long pairBlocks = (long long)n_ml * jchunks;
        const long long totalBlocks = pairBlocks + offBlocks;
        nbrlist_sloop<<<(unsigned)totalBlocks, threads>>>(
            pos, cell, cutoffs, shifts, ml_idx, mm_idx,
            (float*)d_out, n_ml, n_mm, S_img, P, pairBlocks, jchunks, off_aligned);
    } else {
        const long long n_groups   = (P + 3) / 4;
        const long long pairBlocks = (n_groups + threads - 1) / threads;
        const long long totalBlocks = pairBlocks + offBlocks;
        nbrlist_generic<<<(unsigned)totalBlocks, threads>>>(
            pos, cell, cutoffs, shifts, ml_idx, mm_idx,
            (float*)d_out, n_ml, n_mm, S_img, P, pairBlocks, off_aligned);
    }
}

// round 6
// speedup vs baseline: 1.5592x; 1.0009x over previous
#include <cuda_runtime.h>
#include <cuda_bf16.h>
#include <cstdint>

// Inputs: 0 positions f32 (N)*3 | 1 cell f32 9 | 2 cutoffs f32 2
//         3 shifts i32 S*3 | 4 ml_idx i32 | 5 mm_idx i32
// Output (f32 flat): [0,2P) idx_i | [2P,4P) idx_j | [4P,10P) offsets(2P x 3)
//                    [10P,12P) d2_full | [12P,16P) masks(2 x 2P)
// P=(S+1)*n_ml*n_mm.  idx_i=[pi,pj], idx_j=[pj,pi], offsets=[-sv,+sv], d2=[d2,d2].
//
// R6 A/B: plain write-back stores (drop __stcs streaming hint) + 2x larger
// fill blocks. Structure otherwise identical to R5 (s-loop amortization).

__device__ __forceinline__ void load_cell(const float* __restrict__ cell,
                                          float c[9]) {
    #pragma unroll
    for (int u = 0; u < 9; u++) c[u] = __ldg(cell + u);
}

__device__ __forceinline__ void shift_vec(const int* __restrict__ shifts, int s,
                                          const float c[9],
                                          float& svx, float& svy, float& svz) {
    float sf0 = 0.f, sf1 = 0.f, sf2 = 0.f;
    if (s > 0) {
        sf0 = (float)__ldg(shifts + (s - 1) * 3 + 0);
        sf1 = (float)__ldg(shifts + (s - 1) * 3 + 1);
        sf2 = (float)__ldg(shifts + (s - 1) * 3 + 2);
    }
    svx = sf0 * c[0] + sf1 * c[3] + sf2 * c[6];
    svy = sf0 * c[1] + sf1 * c[4] + sf2 * c[7];
    svz = sf0 * c[2] + sf1 * c[5] + sf2 * c[8];
}

// fill blocks: 4096 consecutive float4s per block; lane t writes
// f4 = base + t + u*256 (u<16) -> every STG.128 is a contiguous 512B warp txn
__device__ __forceinline__ void offsets_fill(const int* __restrict__ shifts,
                                             const float c[9],
                                             float* __restrict__ out,
                                             long long fb, long long P,
                                             long long P0, int off_aligned)
{
    const long long tot4 = (6 * P) >> 2;
    const long long base4 = fb * 4096;
    if (base4 >= tot4) return;
    float4* dst = reinterpret_cast<float4*>(out + 4 * P);
    const long long halfF = 3 * P;

    if (off_aligned) {
        const long long fbase = base4 * 4;
        const bool negh = fbase < halfF;
        const long long fl = negh ? fbase : fbase - halfF;
        const int s = (int)(fl / (3 * P0));
        float svx, svy, svz;
        shift_vec(shifts, s, c, svx, svy, svz);
        const float X = negh ? -svx : svx;
        const float Y = negh ? -svy : svy;
        const float Z = negh ? -svz : svz;
        const float4 var[3] = { make_float4(X, Y, Z, X),
                                make_float4(Y, Z, X, Y),
                                make_float4(Z, X, Y, Z) };
        long long f4 = base4 + threadIdx.x;
        int v = (int)(f4 % 3);
        #pragma unroll
        for (int u = 0; u < 16; u++) {
            if (f4 < tot4) dst[f4] = var[v];
            f4 += 256;                          // +256 ≡ +1 (mod 3)
            v++; if (v == 3) v = 0;
        }
    } else {
        for (int u = 0; u < 16; u++) {
            long long f4 = base4 + threadIdx.x + (long long)u * 256;
            if (f4 >= tot4) break;
            #pragma unroll
            for (int w = 0; w < 4; w++) {
                long long f = f4 * 4 + w;
                const bool negh = f < halfF;
                const long long fl = negh ? f : f - halfF;
                const long long row = fl / 3;
                const int comp = (int)(fl - row * 3);
                const int s = (int)(row / P0);
                float svx, svy, svz;
                shift_vec(shifts, s, c, svx, svy, svz);
                float val = (comp == 0) ? svx : (comp == 1) ? svy : svz;
                if (negh) val = -val;
                out[4 * P + f] = val;
            }
        }
    }
}

// ───────────────────────── fast kernel: s-loop amortization ─────────────────
__global__ __launch_bounds__(256)
void nbrlist_sloop(const float* __restrict__ pos,
                   const float* __restrict__ cell,
                   const float* __restrict__ cutoffs,
                   const int*   __restrict__ shifts,
                   const int*   __restrict__ ml_idx,
                   const int*   __restrict__ mm_idx,
                   float* __restrict__ out,
                   int n_ml, int n_mm, int S_img, long long P,
                   long long pairBlocks, int jchunks, int off_aligned)
{
    const long long P0 = (long long)n_ml * n_mm;
    float c[9];
    load_cell(cell, c);

    if (blockIdx.x >= (unsigned)pairBlocks) {
        offsets_fill(shifts, c, out, (long long)blockIdx.x - pairBlocks,
                     P, P0, off_aligned);
        return;
    }

    const int bi = (int)blockIdx.x;
    const int i  = bi / jchunks;
    const int jc = bi - i * jchunks;
    const int j0 = jc * 1024 + (int)threadIdx.x * 4;

    const float cut0 = __ldg(cutoffs + 0), cut1 = __ldg(cutoffs + 1);
    const float c0sq = cut0 * cut0, c1sq = cut1 * cut1;

    const int ia = __ldg(ml_idx + i);
    const float pix0 = __ldg(pos + 3 * ia + 0);
    const float piy0 = __ldg(pos + 3 * ia + 1);
    const float piz0 = __ldg(pos + 3 * ia + 2);

    const int4 jv = __ldg(reinterpret_cast<const int4*>(mm_idx + j0));
    float pjx[4], pjy[4], pjz[4], pjf[4];
    pjf[0] = (float)jv.x; pjf[1] = (float)jv.y;
    pjf[2] = (float)jv.z; pjf[3] = (float)jv.w;

    const bool contig = (jv.w == jv.x + 3) && (((3 * jv.x) & 3) == 0);
    if (contig) {
        const float4* pb = reinterpret_cast<const float4*>(pos + 3 * jv.x);
        const float4 v0 = __ldg(pb + 0);
        const float4 v1 = __ldg(pb + 1);
        const float4 v2 = __ldg(pb + 2);
        pjx[0] = v0.x; pjy[0] = v0.y; pjz[0] = v0.z;
        pjx[1] = v0.w; pjy[1] = v1.x; pjz[1] = v1.y;
        pjx[2] = v1.z; pjy[2] = v1.w; pjz[2] = v2.x;
        pjx[3] = v2.y; pjy[3] = v2.z; pjz[3] = v2.w;
    } else {
        const int jidx[4] = {jv.x, jv.y, jv.z, jv.w};
        #pragma unroll
        for (int u = 0; u < 4; u++) {
            pjx[u] = __ldg(pos + 3 * jidx[u] + 0);
            pjy[u] = __ldg(pos + 3 * jidx[u] + 1);
            pjz[u] = __ldg(pos + 3 * jidx[u] + 2);
        }
    }

    const float fi = (float)ia;
    const float4 v_fi = make_float4(fi, fi, fi, fi);
    const float4 v_pj = make_float4(pjf[0], pjf[1], pjf[2], pjf[3]);

    const long long base_ij = 2 * P;
    const long long base_d2 = 10 * P;
    const long long base_mk = 12 * P;
    const long long prow = (long long)i * n_mm + j0;

    for (int s = 0; s < S_img; s++) {
        float svx, svy, svz;
        shift_vec(shifts, s, c, svx, svy, svz);
        const float pix = pix0 + svx;
        const float piy = piy0 + svy;
        const float piz = piz0 + svz;

        float d2v[4];
        #pragma unroll
        for (int u = 0; u < 4; u++) {
            const float dx = pix - pjx[u];
            const float dy = piy - pjy[u];
            const float dz = piz - pjz[u];
            d2v[u] = dx * dx + dy * dy + dz * dz;
        }

        const long long p = (long long)s * P0 + prow;
        const float4 v_d2 = make_float4(d2v[0], d2v[1], d2v[2], d2v[3]);

        *reinterpret_cast<float4*>(out + p)               = v_fi;
        *reinterpret_cast<float4*>(out + P + p)           = v_pj;
        *reinterpret_cast<float4*>(out + base_ij + p)     = v_pj;
        *reinterpret_cast<float4*>(out + base_ij + P + p) = v_fi;
        *reinterpret_cast<float4*>(out + base_d2 + p)     = v_d2;
        *reinterpret_cast<float4*>(out + base_d2 + P + p) = v_d2;

        const float4 m0 = make_float4(d2v[0] < c0sq ? 1.f : 0.f,
                                      d2v[1] < c0sq ? 1.f : 0.f,
                                      d2v[2] < c0sq ? 1.f : 0.f,
                                      d2v[3] < c0sq ? 1.f : 0.f);
        const float4 m1 = make_float4(d2v[0] < c1sq ? 1.f : 0.f,
                                      d2v[1] < c1sq ? 1.f : 0.f,
                                      d2v[2] < c1sq ? 1.f : 0.f,
                                      d2v[3] < c1sq ? 1.f : 0.f);
        *reinterpret_cast<float4*>(out + base_mk + p)         = m0;
        *reinterpret_cast<float4*>(out + base_mk + P + p)     = m0;
        *reinterpret_cast<float4*>(out + base_mk + 2 * P + p) = m1;
        *reinterpret_cast<float4*>(out + base_mk + 3 * P + p) = m1;
    }
}

// ───────────────────────── generic fallback kernel ──────────────────────────
__global__ __launch_bounds__(256)
void nbrlist_generic(const float* __restrict__ pos,
                     const float* __restrict__ cell,
                     const float* __restrict__ cutoffs,
                     const int*   __restrict__ shifts,
                     const int*   __restrict__ ml_idx,
                     const int*   __restrict__ mm_idx,
                     float* __restrict__ out,
                     int n_ml, int n_mm, int S_img, long long P,
                     long long pairBlocks, int off_aligned)
{
    const long long P0 = (long long)n_ml * n_mm;
    float c[9];
    load_cell(cell, c);

    if (blockIdx.x >= (unsigned)pairBlocks) {
        offsets_fill(shifts, c, out, (long long)blockIdx.x - pairBlocks,
                     P, P0, off_aligned);
        return;
    }

    long long tid = (long long)blockIdx.x * blockDim.x + threadIdx.x;
    long long p0 = tid * 4;
    if (p0 >= P) return;

    const float cut0 = __ldg(cutoffs + 0), cut1 = __ldg(cutoffs + 1);
    const float c0sq = cut0 * cut0, c1sq = cut1 * cut1;

    for (int u = 0; u < 4; u++) {
        long long pp = p0 + u;
        if (pp >= P) break;
        int ss = (int)(pp / P0);
        long long kk = pp - (long long)ss * P0;
        int ii = (int)(kk / n_mm);
        int jj = (int)(kk - (long long)ii * n_mm);

        float svx, svy, svz;
        shift_vec(shifts, ss, c, svx, svy, svz);

        const int ia = __ldg(ml_idx + ii);
        const int ja = __ldg(mm_idx + jj);
        const float dx = __ldg(pos + 3 * ia + 0) - __ldg(pos + 3 * ja + 0) + svx;
        const float dy = __ldg(pos + 3 * ia + 1) - __ldg(pos + 3 * ja + 1) + svy;
        const float dz = __ldg(pos + 3 * ia + 2) - __ldg(pos + 3 * ja + 2) + svz;
        const float d2 = dx * dx + dy * dy + dz * dz;
        const float fi = (float)ia, fj = (float)ja;

        out[pp]         = fi;
        out[P + pp]     = fj;
        out[2 * P + pp] = fj;
        out[3 * P + pp] = fi;
        out[10 * P + pp]     = d2;
        out[10 * P + P + pp] = d2;
        const float m0 = d2 < c0sq ? 1.f : 0.f;
        const float m1 = d2 < c1sq ? 1.f : 0.f;
        out[12 * P + pp]         = m0;
        out[12 * P + P + pp]     = m0;
        out[12 * P + 2 * P + pp] = m1;
        out[12 * P + 3 * P + pp] = m1;
    }
}

extern "C" void kernel_launch(void* const* d_in, const int* in_sizes, int n_in,
                              void* d_out, int out_size)
{
    const float* pos     = (const float*)d_in[0];
    const float* cell    = (const float*)d_in[1];
    const float* cutoffs = (const float*)d_in[2];
    const int*   shifts  = (const int*)d_in[3];
    const int*   ml_idx  = (const int*)d_in[4];
    const int*   mm_idx  = (const int*)d_in[5];

    const int n_ml  = in_sizes[4];
    const int n_mm  = in_sizes[5];
    const int S     = in_sizes[3] / 3;
    const int S_img = S + 1;
    const long long P0 = (long long)n_ml * n_mm;
    const long long P  = (long long)S_img * P0;

    const int threads = 256;

    // fill: 4096 float4s (16384 floats) per block
    const long long tot4      = (6 * P) / 4;
    const long long offBlocks = (tot4 + 4095) / 4096;
    const int off_aligned = (((3 * P0) % 16384) == 0) && (((3 * P) % 16384) == 0)
                            && ((P % 4) == 0) ? 1 : 0;

    const bool fast_ok = (n_mm % 1024 == 0) && ((P % 4) == 0);

    if (fast_ok) {
        const int jchunks = n_mm / 1024;
        const long long pairBlocks = (long long)n_ml * jchunks;
        const long long totalBlocks = pairBlocks + offBlocks;
        nbrlist_sloop<<<(unsigned)totalBlocks, threads>>>(
            pos, cell, cutoffs, shifts, ml_idx, mm_idx,
            (float*)d_out, n_ml, n_mm, S_img, P, pairBlocks, jchunks, off_aligned);
    } else {
        const long long n_groups   = (P + 3) / 4;
        const long long pairBlocks = (n_groups + threads - 1) / threads;
        const long long totalBlocks = pairBlocks + offBlocks;
        nbrlist_generic<<<(unsigned)totalBlocks, threads>>>(
            pos, cell, cutoffs, shifts, ml_idx, mm_idx,
            (float*)d_out, n_ml, n_mm, S_img, P, pairBlocks, off_aligned);
    }
}